// round 5
// baseline (speedup 1.0000x reference)
#include <cuda_runtime.h>
#include <cuda_bf16.h>
#include <cstdint>

// Batched greedy nearest-neighbor selection — single-warp-per-batch version.
// distance: (B, N, N) f32; mask: (B, N) bool (int32/float32/uint8 auto-detected);
// start_idx: (B,) int-or-float; pad_value: scalar int-or-float (fallback N).
// Output (float32): pred (B, N) followed by pred_len (B,).
//
// Inputs identified BY SIZE: distance = largest; mask = largest remaining;
// start_idx = size B; pad = size 1.

#define BIGF 1.0e6f
#define MSK_CAP 4096

__device__ __forceinline__ int decode_scalar(unsigned int w, int N)
{
    return (w <= (unsigned int)N) ? (int)w : (int)__uint_as_float(w);
}

__device__ __forceinline__ unsigned int detect_word_mode(const unsigned char* mraw)
{
    const unsigned int* mw = (const unsigned int*)mraw;
    bool all01 = true, allf = true;
    #pragma unroll 8
    for (int i = 0; i < 64; i++) {
        unsigned int w = mw[i];
        all01 &= (w == 0u || w == 1u);
        allf  &= (w == 0u || w == 0x3f800000u);
    }
    return (all01 || allf) ? 1u : 0u;
}

// ============================================================================
// Fast path: one warp per batch, N <= 1024. Visited mask in one register/lane.
// Element mapping: e = j*128 + lane*4 + p  <->  bit k = j*4 + p  (j<8, p<4).
// ============================================================================
__global__ __launch_bounds__(32, 1)
void greedy_warp_kernel(const float* __restrict__ distance,
                        const unsigned char* __restrict__ mraw,
                        const unsigned int* __restrict__ start_raw,
                        const unsigned int* __restrict__ pad_raw,
                        float* __restrict__ pred,
                        float* __restrict__ pred_len,
                        int N)
{
    const int lane = threadIdx.x;
    const int b    = blockIdx.x;
    const unsigned FULL = 0xffffffffu;

    const float* D = distance + (size_t)b * (size_t)N * (size_t)N;
    float* pred_b = pred + (size_t)b * N;

    // ---- scalar decodes (lane 0) + broadcast ----
    unsigned int wm = 0; int point = 0, pad = N;
    if (lane == 0) {
        wm = detect_word_mode(mraw);
        point = decode_scalar(start_raw[b], N);
        if (pad_raw != nullptr) pad = decode_scalar(*pad_raw, N);
    }
    wm    = __shfl_sync(FULL, wm, 0);
    point = __shfl_sync(FULL, point, 0);
    pad   = __shfl_sync(FULL, pad, 0);

    // ---- build per-lane visited register ----
    const unsigned int* m32 = (const unsigned int*)mraw + (size_t)b * N;
    const unsigned char* m8 = mraw + (size_t)b * N;
    unsigned int vis = 0;
    int cnt = 0;
    #pragma unroll
    for (int j = 0; j < 8; j++) {
        #pragma unroll
        for (int p = 0; p < 4; p++) {
            int e = j * 128 + lane * 4 + p;
            int k = j * 4 + p;
            bool v;
            if (e < N) v = wm ? (m32[e] != 0u) : (m8[e] != 0);
            else       v = true;
            if (v) vis |= (1u << k);
            else   cnt++;
        }
    }
    int rem = (int)__reduce_add_sync(FULL, (unsigned)cnt);
    if (lane == 0) pred_len[b] = (float)rem;

    const unsigned int BIGB = __float_as_uint(BIGF);

    // ---- serial greedy loop: no barriers, no shared memory ----
    int step = 0;
    while (rem > 0) {
        const float* __restrict__ row = D + (size_t)point * N;

        // load 32 elements (8 x LDG.128), apply mask via select
        unsigned int tv[32];
        #pragma unroll
        for (int j = 0; j < 8; j++) {
            int base = j * 128 + lane * 4;
            if (base + 3 < N) {
                float4 v = *reinterpret_cast<const float4*>(row + base);
                tv[j*4+0] = __float_as_uint(v.x);
                tv[j*4+1] = __float_as_uint(v.y);
                tv[j*4+2] = __float_as_uint(v.z);
                tv[j*4+3] = __float_as_uint(v.w);
            } else {
                #pragma unroll
                for (int p = 0; p < 4; p++) {
                    int e = base + p;
                    tv[j*4+p] = (e < N) ? __float_as_uint(row[e]) : BIGB;
                }
            }
        }
        #pragma unroll
        for (int k = 0; k < 32; k++)
            if ((vis >> k) & 1u) tv[k] = BIGB;

        // in-lane adjacent-pair tree, strict left-wins => first-index on ties
        // (leaves are in ascending-e order within the lane)
        unsigned int tk[32];
        #pragma unroll
        for (int k = 0; k < 32; k++) tk[k] = (unsigned)k;
        #pragma unroll
        for (int s = 1; s < 32; s <<= 1) {
            #pragma unroll
            for (int i = 0; i + s < 32; i += 2 * s) {
                if (tv[i + s] < tv[i]) { tv[i] = tv[i + s]; tk[i] = tk[i + s]; }
            }
        }
        unsigned int bv = tv[0];
        unsigned int bk = tk[0];

        // cross-lane: min value, then min matching global index (exact tie-break)
        unsigned int gminv = __reduce_min_sync(FULL, bv);
        unsigned int my_e  = (bk >> 2) * 128u + (unsigned)lane * 4u + (bk & 3u);
        unsigned int cand  = (bv == gminv) ? my_e : 0x7fffffffu;
        unsigned int idx   = __reduce_min_sync(FULL, cand);

        // update (all lanes agree on idx)
        if (lane == 0) pred_b[step] = (float)idx;
        if (lane == (int)((idx >> 2) & 31u))
            vis |= 1u << (((idx >> 7) << 2) | (idx & 3u));
        point = (int)idx;
        rem--;
        step++;
    }

    // ---- pad fill ----
    const float padf = (float)pad;
    for (int s = step + lane; s < N; s += 32) pred_b[s] = padf;
}

// ============================================================================
// Fallback (N > 1024): proven 256-thread CTA-per-batch version.
// ============================================================================
#define NTHREADS 256
#define NWARPS (NTHREADS / 32)

__global__ __launch_bounds__(NTHREADS, 1)
void greedy_nn_kernel(const float* __restrict__ distance,
                      const unsigned char* __restrict__ mraw,
                      const unsigned int* __restrict__ start_raw,
                      const unsigned int* __restrict__ pad_raw,
                      float* __restrict__ pred,
                      float* __restrict__ pred_len,
                      int N)
{
    __shared__ unsigned char s_msk[MSK_CAP];
    __shared__ unsigned long long s_partial[2][NWARPS];
    __shared__ int s_warpcnt[NWARPS];
    __shared__ int s_init[3];

    const int b    = blockIdx.x;
    const int tid  = threadIdx.x;
    const int lane = tid & 31;
    const int wid  = tid >> 5;

    const float* D = distance + (size_t)b * (size_t)N * (size_t)N;
    float* pred_b = pred + (size_t)b * N;
    const int pad = (pad_raw != nullptr) ? decode_scalar(*pad_raw, N) : N;

    if (tid == 0) {
        s_init[0] = (int)detect_word_mode(mraw);
        s_init[1] = decode_scalar(start_raw[b], N);
    }
    __syncthreads();
    const int word_mode = s_init[0];

    int cnt = 0;
    if (word_mode) {
        const unsigned int* m32 = (const unsigned int*)mraw + (size_t)b * N;
        for (int i = tid; i < N && i < MSK_CAP; i += NTHREADS) {
            unsigned char m = (m32[i] != 0u) ? 1 : 0;
            s_msk[i] = m; cnt += (m == 0);
        }
    } else {
        const unsigned char* m8 = mraw + (size_t)b * N;
        for (int i = tid; i < N && i < MSK_CAP; i += NTHREADS) {
            unsigned char m = m8[i] ? 1 : 0;
            s_msk[i] = m; cnt += (m == 0);
        }
    }
    for (int i = N + tid; i < MSK_CAP; i += NTHREADS) s_msk[i] = 1;

    #pragma unroll
    for (int o = 16; o > 0; o >>= 1) cnt += __shfl_down_sync(0xffffffffu, cnt, o);
    if (lane == 0) s_warpcnt[wid] = cnt;
    __syncthreads();
    if (tid == 0) {
        int r = 0;
        #pragma unroll
        for (int w = 0; w < NWARPS; w++) r += s_warpcnt[w];
        s_init[2] = r;
        pred_len[b] = (float)r;
    }
    __syncthreads();

    int rem   = s_init[2];
    int point = s_init[1];

    int step = 0;
    while (rem > 0) {
        const float* __restrict__ row = D + (size_t)point * N;
        const int p = step & 1;
        unsigned long long best = ~0ull;

        for (int base = tid * 4; base < N; base += NTHREADS * 4) {
            if (base + 3 < N) {
                float4 v = *reinterpret_cast<const float4*>(row + base);
                unsigned int mw = *reinterpret_cast<const unsigned int*>(s_msk + base);
                float v0 = (mw & 0x000000ffu) ? BIGF : v.x;
                float v1 = (mw & 0x0000ff00u) ? BIGF : v.y;
                float v2 = (mw & 0x00ff0000u) ? BIGF : v.z;
                float v3 = (mw & 0xff000000u) ? BIGF : v.w;
                unsigned long long k0 = ((unsigned long long)__float_as_uint(v0) << 32) | (unsigned)(base + 0);
                unsigned long long k1 = ((unsigned long long)__float_as_uint(v1) << 32) | (unsigned)(base + 1);
                unsigned long long k2 = ((unsigned long long)__float_as_uint(v2) << 32) | (unsigned)(base + 2);
                unsigned long long k3 = ((unsigned long long)__float_as_uint(v3) << 32) | (unsigned)(base + 3);
                unsigned long long ka = k0 < k1 ? k0 : k1;
                unsigned long long kb = k2 < k3 ? k2 : k3;
                unsigned long long kc = ka < kb ? ka : kb;
                best = kc < best ? kc : best;
            } else {
                for (int j = base; j < N; j++) {
                    float v = s_msk[j] ? BIGF : row[j];
                    unsigned long long k = ((unsigned long long)__float_as_uint(v) << 32) | (unsigned)j;
                    best = k < best ? k : best;
                }
            }
        }

        #pragma unroll
        for (int o = 16; o > 0; o >>= 1) {
            unsigned long long other = __shfl_down_sync(0xffffffffu, best, o);
            best = other < best ? other : best;
        }
        if (lane == 0) s_partial[p][wid] = best;
        __syncthreads();

        unsigned long long bb = s_partial[p][0];
        #pragma unroll
        for (int w = 1; w < NWARPS; w++) {
            unsigned long long q = s_partial[p][w];
            bb = q < bb ? q : bb;
        }
        int idx = (int)(bb & 0xffffffffu);
        s_msk[idx] = 1;
        point = idx;
        rem--;
        if (tid == 0) pred_b[step] = (float)idx;
        step++;
    }

    const float padf = (float)pad;
    for (int s = step + tid; s < N; s += NTHREADS) pred_b[s] = padf;
}

extern "C" void kernel_launch(void* const* d_in, const int* in_sizes, int n_in,
                              void* d_out, int out_size)
{
    // ---- identify inputs by size (order-independent) ----
    int di = 0;
    for (int i = 1; i < n_in; i++)
        if (in_sizes[i] > in_sizes[di]) di = i;              // distance (B*N*N)

    int mi = -1;
    for (int i = 0; i < n_in; i++) {
        if (i == di) continue;
        if (mi < 0 || in_sizes[i] > in_sizes[mi]) mi = i;    // mask (B*N)
    }

    const long long S_d = in_sizes[di];
    const long long S_m = in_sizes[mi];
    const int N = (int)(S_d / S_m);
    const int B = (int)(S_m / N);

    int si = -1, pi = -1;
    for (int i = 0; i < n_in; i++) {
        if (i == di || i == mi) continue;
        if (in_sizes[i] == B) si = i;
        else if (in_sizes[i] == 1) pi = i;
    }

    const float*         distance  = (const float*)d_in[di];
    const unsigned char* mask      = (const unsigned char*)d_in[mi];
    const unsigned int*  start_raw = (const unsigned int*)d_in[si];
    const unsigned int*  pad_raw   = (pi >= 0) ? (const unsigned int*)d_in[pi] : nullptr;

    float* pred     = (float*)d_out;          // (B, N) float32
    float* pred_len = pred + (size_t)B * N;   // (B,)

    if (N <= 1024) {
        greedy_warp_kernel<<<B, 32>>>(distance, mask, start_raw, pad_raw,
                                      pred, pred_len, N);
    } else {
        greedy_nn_kernel<<<B, NTHREADS>>>(distance, mask, start_raw, pad_raw,
                                          pred, pred_len, N);
    }
}